// round 13
// baseline (speedup 1.0000x reference)
#include <cuda_runtime.h>
#include <cuda_fp16.h>
#include <cstdint>

#define KCAP 512
#define DDIM 1024
#define BMAX 16384
#define PAD  520

// fp8 scaling (e4m3 min-normal is 2^-6; keep operands in normal range)
#define AS_SC 256.0f     // At scale
#define BS_SC 64.0f      // b scale
#define XS_SC 8.0f       // x scale
#define WS_SC 64.0f      // W scale
#define DSC   (1.0f / (AS_SC * BS_SC))          // k_main d unscale
#define NSC   (1.0f / (XS_SC * XS_SC * WS_SC * WS_SC))  // norm_sq unscale

// ---------------- device scratch (no allocations allowed) ----------------
__device__ __align__(16) float g_At[KCAP * KCAP];   // fp32 0.1*A_diff^T (for k_prep)
// Lane-major e4m3 At for k_main B fragments (m16n8k32):
// uint idx = (((gg*16 + w)*2 + jj)*32 + lane)*4 + tpar*2 + {0:b0,1:b1}
//   gg = k32 chunk (0..15), w = warp n-stripe, jj = tile pair, tile t = jj*2+tpar
//   n = w*32 + t*8 + (lane>>2); b0 = At[k0..k0+3, n], b1 = At[k0+16..k0+19, n], k0 = gg*32+4*(lane&3)
__device__ __align__(16) unsigned g_AtB[16 * 16 * 2 * 32 * 4];
// x as e4m3 A-fragments: [(rt*32+gg)*32+lane] uint4 {a0,a1,a2,a3}
//   rt = row-tile of 16, gg = k32 chunk (32); r = lane>>2, k0 = gg*32+4*(lane&3)
//   a0 = x[rt*16+r][k0..+3], a1 = row+8, a2 = k0+16, a3 = row+8 k0+16
__device__ uint4 g_xB8[1024 * 32 * 32];
// W as e4m3 B-fragments: [(ctp*32+gg)*32+lane] uint4 {b0_e,b1_e,b0_o,b1_o}
//   ctp = col-tile-pair of 16; n_e = ctp*16+(lane>>2), n_o = +8
__device__ uint4 g_wB8[32 * 32 * 32];
__device__ float g_nsp[4 * BMAX];
__device__ float g_agr[BMAX];
__device__ __align__(16) float g_u1[KCAP];
__device__ __align__(16) float g_w1[KCAP];
__device__ float g_sc[2];                            // {1/T_eff, c}

// ---------------- helpers ----------------
__device__ __forceinline__ float blkMax256(float v, float* sc) {
    #pragma unroll
    for (int o = 16; o > 0; o >>= 1) v = fmaxf(v, __shfl_xor_sync(0xffffffffu, v, o));
    if ((threadIdx.x & 31) == 0) sc[threadIdx.x >> 5] = v;
    __syncthreads();
    float r = sc[0];
    #pragma unroll
    for (int i = 1; i < 8; i++) r = fmaxf(r, sc[i]);
    __syncthreads();
    return r;
}
__device__ __forceinline__ float blkSum256(float v, float* sc) {
    #pragma unroll
    for (int o = 16; o > 0; o >>= 1) v += __shfl_xor_sync(0xffffffffu, v, o);
    if ((threadIdx.x & 31) == 0) sc[threadIdx.x >> 5] = v;
    __syncthreads();
    float r = sc[0];
    #pragma unroll
    for (int i = 1; i < 8; i++) r += sc[i];
    __syncthreads();
    return r;
}
// pack 4 floats to e4m3x4 (byte0 = f0)
__device__ __forceinline__ unsigned pack4e4(float f0, float f1, float f2, float f3) {
    unsigned short p01, p23;
    asm("cvt.rn.satfinite.e4m3x2.f32 %0, %1, %2;" : "=h"(p01) : "f"(f1), "f"(f0));
    asm("cvt.rn.satfinite.e4m3x2.f32 %0, %1, %2;" : "=h"(p23) : "f"(f3), "f"(f2));
    return (unsigned)p01 | ((unsigned)p23 << 16);
}

#define MMA_E4(c, a0, a1, a2, a3, b0, b1)                                              \
    asm volatile(                                                                       \
        "mma.sync.aligned.m16n8k32.row.col.f32.e4m3.e4m3.f32 "                          \
        "{%0,%1,%2,%3},{%4,%5,%6,%7},{%8,%9},{%0,%1,%2,%3};"                            \
        : "+f"((c)[0]), "+f"((c)[1]), "+f"((c)[2]), "+f"((c)[3])                        \
        : "r"(a0), "r"(a1), "r"(a2), "r"(a3), "r"(b0), "r"(b1))

// ---------------- P0: scalars ----------------
__global__ void k_scalars(const float* __restrict__ lT, const float* __restrict__ lc,
                          const void* __restrict__ tp) {
    if (threadIdx.x == 0) {
        unsigned w = *(const unsigned*)tp;
        float ft = __uint_as_float(w);
        float tempv = (fabsf(ft) > 1e-30f && fabsf(ft) < 1e30f) ? ft : (float)(int)w;
        float T = fminf(fmaxf(expf(lT[0]) * tempv, 0.05f), 10.0f);
        g_sc[0] = 1.0f / T;
        g_sc[1] = fminf(fmaxf(expf(lc[0]), 0.01f), 10.0f);
    }
}

// ---------------- P1: symmetric softmax -> At fp32 + lane-major e4m3 ----------------
__global__ void __launch_bounds__(256) k_adiff(const float* __restrict__ A) {
    __shared__ float scr[8];
    __shared__ float col[KCAP];
    const int j = blockIdx.x, tid = threadIdx.x;
    float v0 = 0.5f * (A[j * KCAP + tid]       + A[tid * KCAP + j]);
    float v1 = 0.5f * (A[j * KCAP + tid + 256] + A[(tid + 256) * KCAP + j]);
    float M = blkMax256(fmaxf(v0, v1), scr);
    float e0 = __expf(v0 - M), e1 = __expf(v1 - M);
    float S = blkSum256(e0 + e1, scr);
    float r = 0.1f / S;
    float a0 = e0 * r, a1 = e1 * r;
    g_At[tid * KCAP + j]         = a0;
    g_At[(tid + 256) * KCAP + j] = a1;
    col[tid] = a0; col[tid + 256] = a1;
    __syncthreads();
    if (tid < 64) {
        int gg = tid >> 2, kq = tid & 3;
        int k0 = gg * 32 + 4 * kq;
        float4 c0 = *(const float4*)&col[k0];
        float4 c1 = *(const float4*)&col[k0 + 16];
        unsigned b0 = pack4e4(c0.x * AS_SC, c0.y * AS_SC, c0.z * AS_SC, c0.w * AS_SC);
        unsigned b1 = pack4e4(c1.x * AS_SC, c1.y * AS_SC, c1.z * AS_SC, c1.w * AS_SC);
        int w = j >> 5, t = (j >> 3) & 3, jj = t >> 1, tpar = t & 1, nq = j & 7;
        int lane = nq * 4 + kq;
        unsigned base = (unsigned)((((gg * 16 + w) * 2 + jj) * 32 + lane) * 4 + tpar * 2);
        g_AtB[base]     = b0;
        g_AtB[base + 1] = b1;
    }
}

// ---------------- P2: fold iteration 0 ----------------
__global__ void __launch_bounds__(256) k_prep(const float* __restrict__ brun) {
    __shared__ float br[KCAP];
    __shared__ float sg[KCAP];
    __shared__ float scr[8];
    const int tid = threadIdx.x;
    const float invT = g_sc[0];
    float v0 = brun[tid], v1 = brun[tid + 256];
    br[tid] = v0; br[tid + 256] = v1;
    float M = blkMax256(fmaxf(v0, v1), scr);
    float e0 = __expf((v0 - M) * invT), e1 = __expf((v1 - M) * invT);
    float S = blkSum256(e0 + e1, scr);
    float is = 1.0f / S;
    sg[tid] = e0 * is; sg[tid + 256] = e1 * is;
    __syncthreads();
    const int j = blockIdx.x * 256 + tid;
    float u = 0.0f, w = 0.0f;
    #pragma unroll 8
    for (int k = 0; k < KCAP; k++) {
        float at = g_At[k * KCAP + j];
        u = fmaf(br[k], at, u);
        w = fmaf(sg[k], at, w);
    }
    g_u1[j] = br[j] + u;
    g_w1[j] = sg[j] + w;
}

// ---------------- P3a: x -> e4m3 A-fragment layout ----------------
#define CXS 1032
__global__ void __launch_bounds__(256) k_convx(const float* __restrict__ x) {
    extern __shared__ float xs[];   // [16][CXS]
    const int rt = blockIdx.x, tid = threadIdx.x;
    for (int i = tid; i < 16 * 256; i += 256) {
        int row = i >> 8, c4 = (i & 255) * 4;
        *(float4*)&xs[row * CXS + c4] =
            *(const float4*)&x[(size_t)(rt * 16 + row) * DDIM + c4];
    }
    __syncthreads();
    #pragma unroll
    for (int i = 0; i < 4; i++) {
        int f = i * 256 + tid;           // 1024 fragments
        int gg = f >> 5, lane = f & 31;
        int r = lane >> 2, k0 = gg * 32 + 4 * (lane & 3);
        float4 q0 = *(const float4*)&xs[r * CXS + k0];
        float4 q1 = *(const float4*)&xs[(r + 8) * CXS + k0];
        float4 q2 = *(const float4*)&xs[r * CXS + k0 + 16];
        float4 q3 = *(const float4*)&xs[(r + 8) * CXS + k0 + 16];
        uint4 v;
        v.x = pack4e4(q0.x * XS_SC, q0.y * XS_SC, q0.z * XS_SC, q0.w * XS_SC);
        v.y = pack4e4(q1.x * XS_SC, q1.y * XS_SC, q1.z * XS_SC, q1.w * XS_SC);
        v.z = pack4e4(q2.x * XS_SC, q2.y * XS_SC, q2.z * XS_SC, q2.w * XS_SC);
        v.w = pack4e4(q3.x * XS_SC, q3.y * XS_SC, q3.z * XS_SC, q3.w * XS_SC);
        g_xB8[(size_t)(rt * 32 + gg) * 32 + lane] = v;
    }
}

// ---------------- P3b: W -> e4m3 B-fragment layout ----------------
__global__ void __launch_bounds__(256) k_convw(const float* __restrict__ W) {
    extern __shared__ float xs[];   // [16][CXS]
    const int ctp = blockIdx.x, tid = threadIdx.x;
    for (int i = tid; i < 16 * 256; i += 256) {
        int row = i >> 8, c4 = (i & 255) * 4;
        *(float4*)&xs[row * CXS + c4] =
            *(const float4*)&W[(size_t)(ctp * 16 + row) * DDIM + c4];
    }
    __syncthreads();
    #pragma unroll
    for (int i = 0; i < 4; i++) {
        int f = i * 256 + tid;
        int gg = f >> 5, lane = f & 31;
        int nl = lane >> 2, k0 = gg * 32 + 4 * (lane & 3);
        float4 q0 = *(const float4*)&xs[nl * CXS + k0];
        float4 q1 = *(const float4*)&xs[nl * CXS + k0 + 16];
        float4 q2 = *(const float4*)&xs[(nl + 8) * CXS + k0];
        float4 q3 = *(const float4*)&xs[(nl + 8) * CXS + k0 + 16];
        uint4 v;
        v.x = pack4e4(q0.x * WS_SC, q0.y * WS_SC, q0.z * WS_SC, q0.w * WS_SC);
        v.y = pack4e4(q1.x * WS_SC, q1.y * WS_SC, q1.z * WS_SC, q1.w * WS_SC);
        v.z = pack4e4(q2.x * WS_SC, q2.y * WS_SC, q2.z * WS_SC, q2.w * WS_SC);
        v.w = pack4e4(q3.x * WS_SC, q3.y * WS_SC, q3.z * WS_SC, q3.w * WS_SC);
        g_wB8[(size_t)(ctp * 32 + gg) * 32 + lane] = v;
    }
}

// ---------------- P3c: barrier-free fp8 GEMM + row sum-of-squares ----------------
__global__ void __launch_bounds__(256, 2) k_norm(int B) {
    __shared__ float red2[128 * 2];
    const int tid  = threadIdx.x;
    const int lane = tid & 31;
    const int w    = tid >> 5;
    const int mrow = (w & 3) * 32;
    const int cg   = w >> 2;
    const int yg   = blockIdx.y;

    const uint4* xb = g_xB8 + ((size_t)(blockIdx.x * 8 + (w & 3) * 2) * 32) * 32 + lane;
    const uint4* wb = g_wB8 + ((size_t)(yg * 8 + cg * 4) * 32) * 32 + lane;

    float acc[2][8][4];
    #pragma unroll
    for (int mt = 0; mt < 2; mt++)
        #pragma unroll
        for (int nt = 0; nt < 8; nt++)
            #pragma unroll
            for (int q = 0; q < 4; q++) acc[mt][nt][q] = 0.0f;

    uint4 A[2], Bv[4];
    #pragma unroll
    for (int mt = 0; mt < 2; mt++) A[mt] = xb[mt * 1024];
    #pragma unroll
    for (int p = 0; p < 4; p++) Bv[p] = wb[p * 1024];

    #pragma unroll 4
    for (int gg = 0; gg < 32; gg++) {
        uint4 A2[2], B2[4];
        if (gg < 31) {
            const uint4* xn = xb + (gg + 1) * 32;
            const uint4* wn = wb + (gg + 1) * 32;
            #pragma unroll
            for (int mt = 0; mt < 2; mt++) A2[mt] = xn[mt * 1024];
            #pragma unroll
            for (int p = 0; p < 4; p++) B2[p] = wn[p * 1024];
        }
        #pragma unroll
        for (int mt = 0; mt < 2; mt++) {
            #pragma unroll
            for (int p = 0; p < 4; p++) {
                MMA_E4(acc[mt][2 * p],     A[mt].x, A[mt].y, A[mt].z, A[mt].w, Bv[p].x, Bv[p].y);
                MMA_E4(acc[mt][2 * p + 1], A[mt].x, A[mt].y, A[mt].z, A[mt].w, Bv[p].z, Bv[p].w);
            }
        }
        #pragma unroll
        for (int mt = 0; mt < 2; mt++) A[mt] = A2[mt];
        #pragma unroll
        for (int p = 0; p < 4; p++) Bv[p] = B2[p];
    }

    #pragma unroll
    for (int mt = 0; mt < 2; mt++) {
        #pragma unroll
        for (int h = 0; h < 2; h++) {
            float s = 0.0f;
            #pragma unroll
            for (int nt = 0; nt < 8; nt++) {
                float a = acc[mt][nt][2 * h], b = acc[mt][nt][2 * h + 1];
                s = fmaf(a, a, fmaf(b, b, s));
            }
            s += __shfl_xor_sync(0xffffffffu, s, 1);
            s += __shfl_xor_sync(0xffffffffu, s, 2);
            if ((lane & 3) == 0) {
                int rloc = mrow + mt * 16 + (lane >> 2) + h * 8;
                red2[rloc * 2 + cg] = s * NSC;
            }
        }
    }
    __syncthreads();
    if (tid < 128) {
        float s = red2[tid * 2] + red2[tid * 2 + 1];
        g_nsp[(size_t)yg * B + blockIdx.x * 128 + tid] = s;
    }
}

// ---------------- P4: agreement ----------------
__global__ void k_agree(int B) {
    int i = blockIdx.x * 256 + threadIdx.x;
    if (i < B) {
        float c = g_sc[1];
        float ns = g_nsp[i] + g_nsp[B + i] + g_nsp[2 * B + i] + g_nsp[3 * B + i];
        ns = fmaxf(ns, 1e-10f);
        float sc2 = c * ns / (1.0f + c * ns);
        g_agr[i] = sc2 * sqrtf(ns);
    }
}

// ---------------- MAIN: barrier-free fp8 GEMM (B via LDG, A via e4m3 smem) ----------------
// smem: b_s[64][520] f32 | bh[64][132] u32 (e4m3 quads) | red[512] | agrs[64]
#define BHS8 132
#define SMEM_MAIN_BYTES ((64 * PAD + 512 + 64) * 4 + 64 * BHS8 * 4)

__global__ void __launch_bounds__(512, 1) k_main(float* __restrict__ out) {
    extern __shared__ float sm[];
    float*    b_s  = sm;                              // [64][PAD]
    unsigned* bh   = (unsigned*)(sm + 64 * PAD);      // [64][BHS8]
    float*    red  = (float*)(bh + 64 * BHS8);        // [512]
    float*    agrs = red + 512;                       // [64]

    const int tid  = threadIdx.x;
    const int lane = tid & 31;
    const int wrp  = tid >> 5;
    const int row0 = blockIdx.x * 64;
    const float invT = g_sc[0];

    const int r  = tid >> 3;
    const int t8 = tid & 7;
    float* base = b_s + r * PAD + t8 * 4;
    unsigned* bhrow = bh + r * BHS8 + t8;

    if (tid < 64) agrs[tid] = g_agr[row0 + tid];
    float uj = g_u1[tid & 511];
    float wj = g_w1[tid & 511];
    __syncthreads();
    #pragma unroll 8
    for (int r2 = 0; r2 < 64; r2++)
        b_s[r2 * PAD + tid] = fmaf(agrs[r2], wj, uj);
    __syncthreads();

    // B fragment gmem base for this warp (uint4 units); gg stride = 1024 uint4
    const uint4* bbase = (const uint4*)g_AtB + (wrp * 2) * 32 + lane;

    for (int it = 0; it < 4; it++) {
        // ---- b += a * softmax(b/T); also write e4m3 copy (x BS_SC) to bh ----
        float mx = -3.4e38f;
        #pragma unroll
        for (int j = 0; j < 16; j++) {
            float4 v = *(const float4*)(base + j * 32);
            mx = fmaxf(mx, fmaxf(fmaxf(v.x, v.y), fmaxf(v.z, v.w)));
        }
        red[tid] = mx; __syncthreads();
        float m = red[r * 8];
        #pragma unroll
        for (int q = 1; q < 8; q++) m = fmaxf(m, red[r * 8 + q]);
        __syncthreads();
        float s = 0.0f;
        #pragma unroll
        for (int j = 0; j < 16; j++) {
            float4 v = *(const float4*)(base + j * 32);
            s += __expf((v.x - m) * invT) + __expf((v.y - m) * invT)
               + __expf((v.z - m) * invT) + __expf((v.w - m) * invT);
        }
        red[tid] = s; __syncthreads();
        float S = red[r * 8];
        #pragma unroll
        for (int q = 1; q < 8; q++) S += red[r * 8 + q];
        float aS = agrs[r] / S;
        #pragma unroll
        for (int j = 0; j < 16; j++) {
            float4 v = *(const float4*)(base + j * 32);
            v.x = fmaf(aS, __expf((v.x - m) * invT), v.x);
            v.y = fmaf(aS, __expf((v.y - m) * invT), v.y);
            v.z = fmaf(aS, __expf((v.z - m) * invT), v.z);
            v.w = fmaf(aS, __expf((v.w - m) * invT), v.w);
            *(float4*)(base + j * 32) = v;
            bhrow[j * 8] = pack4e4(v.x * BS_SC, v.y * BS_SC, v.z * BS_SC, v.w * BS_SC);
        }
        __syncthreads();

        // ---- d = b @ At (e4m3 k32), zero-barrier GEMM ----
        float acc[4][4][4];
        #pragma unroll
        for (int mt = 0; mt < 4; mt++)
            #pragma unroll
            for (int nt = 0; nt < 4; nt++)
                #pragma unroll
                for (int q = 0; q < 4; q++) acc[mt][nt][q] = 0.0f;

        uint4 B0 = bbase[0], B1 = bbase[32];
        #pragma unroll 4
        for (int gg = 0; gg < 16; gg++) {
            uint4 C0, C1;
            if (gg < 15) {
                const uint4* nb = bbase + (gg + 1) * 1024;
                C0 = nb[0]; C1 = nb[32];
            }
            const int kb = gg * 8 + (lane & 3);
            #pragma unroll
            for (int mt = 0; mt < 4; mt++) {
                int ra = (mt * 16 + (lane >> 2)) * BHS8 + kb;
                unsigned a0 = bh[ra];
                unsigned a1 = bh[ra + 8 * BHS8];
                unsigned a2 = bh[ra + 4];
                unsigned a3 = bh[ra + 8 * BHS8 + 4];
                MMA_E4(acc[mt][0], a0, a1, a2, a3, B0.x, B0.y);
                MMA_E4(acc[mt][1], a0, a1, a2, a3, B0.z, B0.w);
                MMA_E4(acc[mt][2], a0, a1, a2, a3, B1.x, B1.y);
                MMA_E4(acc[mt][3], a0, a1, a2, a3, B1.z, B1.w);
            }
            B0 = C0; B1 = C1;
        }

        // ---- b += d / (AS_SC*BS_SC) ----
        #pragma unroll
        for (int mt = 0; mt < 4; mt++) {
            int row = mt * 16 + (lane >> 2);
            #pragma unroll
            for (int nt = 0; nt < 4; nt++) {
                int col = wrp * 32 + nt * 8 + 2 * (lane & 3);
                float* p = b_s + row * PAD + col;
                p[0]           += acc[mt][nt][0] * DSC;
                p[1]           += acc[mt][nt][1] * DSC;
                p[8 * PAD]     += acc[mt][nt][2] * DSC;
                p[8 * PAD + 1] += acc[mt][nt][3] * DSC;
            }
        }
        __syncthreads();
    }

    // ---- theta = softmax(b/T) -> out ----
    {
        float mx = -3.4e38f;
        #pragma unroll
        for (int j = 0; j < 16; j++) {
            float4 v = *(const float4*)(base + j * 32);
            mx = fmaxf(mx, fmaxf(fmaxf(v.x, v.y), fmaxf(v.z, v.w)));
        }
        red[tid] = mx; __syncthreads();
        float m = red[r * 8];
        #pragma unroll
        for (int q = 1; q < 8; q++) m = fmaxf(m, red[r * 8 + q]);
        __syncthreads();
        float s = 0.0f;
        #pragma unroll
        for (int j = 0; j < 16; j++) {
            float4 v = *(const float4*)(base + j * 32);
            s += __expf((v.x - m) * invT) + __expf((v.y - m) * invT)
               + __expf((v.z - m) * invT) + __expf((v.w - m) * invT);
        }
        red[tid] = s; __syncthreads();
        float S = red[r * 8];
        #pragma unroll
        for (int q = 1; q < 8; q++) S += red[r * 8 + q];
        float iS = 1.0f / S;
        float* op = out + (size_t)(row0 + r) * KCAP + t8 * 4;
        #pragma unroll
        for (int j = 0; j < 16; j++) {
            float4 v = *(const float4*)(base + j * 32);
            float4 o;
            o.x = __expf((v.x - m) * invT) * iS;
            o.y = __expf((v.y - m) * invT) * iS;
            o.z = __expf((v.z - m) * invT) * iS;
            o.w = __expf((v.w - m) * invT) * iS;
            *(float4*)(op + j * 32) = o;
        }
    }
}

// ---------------- launcher ----------------
extern "C" void kernel_launch(void* const* d_in, const int* in_sizes, int n_in,
                              void* d_out, int out_size) {
    const float* x    = (const float*)d_in[0];
    const float* W    = (const float*)d_in[1];
    const float* A    = (const float*)d_in[2];
    const float* lT   = (const float*)d_in[3];
    const float* lc   = (const float*)d_in[4];
    const float* brun = (const float*)d_in[5];
    const void*  temp = d_in[6];
    const int B = in_sizes[0] / DDIM;   // 16384
    const int CONV_SMEM = 16 * CXS * 4;

    cudaFuncSetAttribute(k_main, cudaFuncAttributeMaxDynamicSharedMemorySize,
                         SMEM_MAIN_BYTES);
    cudaFuncSetAttribute(k_convx, cudaFuncAttributeMaxDynamicSharedMemorySize,
                         CONV_SMEM);
    cudaFuncSetAttribute(k_convw, cudaFuncAttributeMaxDynamicSharedMemorySize,
                         CONV_SMEM);

    k_scalars<<<1, 32>>>(lT, lc, temp);
    k_adiff<<<KCAP, 256>>>(A);
    k_prep<<<2, 256>>>(brun);
    k_convx<<<B / 16, 256, CONV_SMEM>>>(x);
    k_convw<<<KCAP / 16, 256, CONV_SMEM>>>(W);
    k_norm<<<dim3(B / 128, 4), 256>>>(B);
    k_agree<<<(B + 255) / 256, 256>>>(B);
    k_main<<<B / 64, 512, SMEM_MAIN_BYTES>>>((float*)d_out);
}

// round 14
// speedup vs baseline: 1.3005x; 1.3005x over previous
#include <cuda_runtime.h>
#include <cuda_fp16.h>
#include <cstdint>

#define KCAP 512
#define DDIM 1024
#define BMAX 16384
#define PAD  520

// ---------------- device scratch (no allocations allowed) ----------------
__device__ __align__(16) float g_At[KCAP * KCAP];   // fp32 0.1*A_diff^T (for k_prep)
// Lane-major f16 At for k_main B fragments (see R11/R12)
__device__ __align__(16) unsigned g_AtB[32 * 16 * 2 * 32 * 4];
// x as mma A-fragments: [(rt*64+gg)*32+lane] uint4 {a0,a1,a2,a3}  (f16x2 k-pairs)
__device__ uint4 g_xB[1024 * 64 * 32];
// W as mma B-fragments: [(ctp*64+gg)*32+lane] uint4 {b0_e, b1_e, b0_o, b1_o}
__device__ uint4 g_wB[32 * 64 * 32];
__device__ float g_nsp[4 * BMAX];
__device__ float g_agr[BMAX];
__device__ __align__(16) float g_u1[KCAP];
__device__ __align__(16) float g_w1[KCAP];
__device__ float g_sc[2];                            // {1/T_eff, c}

// ---------------- helpers ----------------
__device__ __forceinline__ float blkMax256(float v, float* sc) {
    #pragma unroll
    for (int o = 16; o > 0; o >>= 1) v = fmaxf(v, __shfl_xor_sync(0xffffffffu, v, o));
    if ((threadIdx.x & 31) == 0) sc[threadIdx.x >> 5] = v;
    __syncthreads();
    float r = sc[0];
    #pragma unroll
    for (int i = 1; i < 8; i++) r = fmaxf(r, sc[i]);
    __syncthreads();
    return r;
}
__device__ __forceinline__ float blkSum256(float v, float* sc) {
    #pragma unroll
    for (int o = 16; o > 0; o >>= 1) v += __shfl_xor_sync(0xffffffffu, v, o);
    if ((threadIdx.x & 31) == 0) sc[threadIdx.x >> 5] = v;
    __syncthreads();
    float r = sc[0];
    #pragma unroll
    for (int i = 1; i < 8; i++) r += sc[i];
    __syncthreads();
    return r;
}
__device__ __forceinline__ unsigned packhf(float lo, float hi) {
    unsigned r;
    asm("cvt.rn.f16x2.f32 %0, %1, %2;" : "=r"(r) : "f"(hi), "f"(lo));
    return r;
}

#define MMA_F16(c, a0, a1, a2, a3, b0, b1)                                             \
    asm volatile(                                                                       \
        "mma.sync.aligned.m16n8k16.row.col.f32.f16.f16.f32 "                            \
        "{%0,%1,%2,%3},{%4,%5,%6,%7},{%8,%9},{%0,%1,%2,%3};"                            \
        : "+f"((c)[0]), "+f"((c)[1]), "+f"((c)[2]), "+f"((c)[3])                        \
        : "r"(a0), "r"(a1), "r"(a2), "r"(a3), "r"(b0), "r"(b1))

// ---------------- P0: scalars ----------------
__global__ void k_scalars(const float* __restrict__ lT, const float* __restrict__ lc,
                          const void* __restrict__ tp) {
    if (threadIdx.x == 0) {
        unsigned w = *(const unsigned*)tp;
        float ft = __uint_as_float(w);
        float tempv = (fabsf(ft) > 1e-30f && fabsf(ft) < 1e30f) ? ft : (float)(int)w;
        float T = fminf(fmaxf(expf(lT[0]) * tempv, 0.05f), 10.0f);
        g_sc[0] = 1.0f / T;
        g_sc[1] = fminf(fmaxf(expf(lc[0]), 0.01f), 10.0f);
    }
}

// ---------------- P1: symmetric softmax -> At fp32 + lane-major f16 ----------------
__global__ void __launch_bounds__(256) k_adiff(const float* __restrict__ A) {
    __shared__ float scr[8];
    __shared__ float col[KCAP];
    const int j = blockIdx.x, tid = threadIdx.x;
    float v0 = 0.5f * (A[j * KCAP + tid]       + A[tid * KCAP + j]);
    float v1 = 0.5f * (A[j * KCAP + tid + 256] + A[(tid + 256) * KCAP + j]);
    float M = blkMax256(fmaxf(v0, v1), scr);
    float e0 = __expf(v0 - M), e1 = __expf(v1 - M);
    float S = blkSum256(e0 + e1, scr);
    float r = 0.1f / S;
    float a0 = e0 * r, a1 = e1 * r;
    g_At[tid * KCAP + j]         = a0;
    g_At[(tid + 256) * KCAP + j] = a1;
    col[tid] = a0; col[tid + 256] = a1;
    __syncthreads();
    if (tid < 128) {
        int gg = tid >> 2, kq = tid & 3;
        int p0 = gg * 8 + kq;
        int p1 = p0 + 4;
        uint2 v;
        v.x = packhf(col[2 * p0], col[2 * p0 + 1]);
        v.y = packhf(col[2 * p1], col[2 * p1 + 1]);
        int w = j >> 5, t = (j >> 3) & 3, jj = t >> 1, tpar = t & 1, nq = j & 7;
        int lane = nq * 4 + kq;
        unsigned base = (unsigned)((((gg * 16 + w) * 2 + jj) * 32 + lane) * 4 + tpar * 2);
        g_AtB[base]     = v.x;
        g_AtB[base + 1] = v.y;
    }
}

// ---------------- P2: fold iteration 0 (parallelized: 16 blocks x 8-way k-split) ----------------
__global__ void __launch_bounds__(256) k_prep(const float* __restrict__ brun) {
    __shared__ float br[KCAP];
    __shared__ float sg[KCAP];
    __shared__ float scr[8];
    __shared__ float redu[256];
    __shared__ float redw[256];
    const int tid = threadIdx.x;
    const float invT = g_sc[0];
    float v0 = brun[tid], v1 = brun[tid + 256];
    br[tid] = v0; br[tid + 256] = v1;
    float M = blkMax256(fmaxf(v0, v1), scr);
    float e0 = __expf((v0 - M) * invT), e1 = __expf((v1 - M) * invT);
    float S = blkSum256(e0 + e1, scr);
    float is = 1.0f / S;
    sg[tid] = e0 * is; sg[tid + 256] = e1 * is;
    __syncthreads();
    const int j = blockIdx.x * 32 + (tid & 31);
    const int ks = tid >> 5;           // 0..7
    float u = 0.0f, w = 0.0f;
    #pragma unroll 8
    for (int k = ks * 64; k < ks * 64 + 64; k++) {
        float at = g_At[k * KCAP + j];
        u = fmaf(br[k], at, u);
        w = fmaf(sg[k], at, w);
    }
    redu[tid] = u; redw[tid] = w;
    __syncthreads();
    if (tid < 32) {
        float uu = 0.0f, ww = 0.0f;
        #pragma unroll
        for (int s2 = 0; s2 < 8; s2++) { uu += redu[tid + 32 * s2]; ww += redw[tid + 32 * s2]; }
        int jj = blockIdx.x * 32 + tid;
        g_u1[jj] = br[jj] + uu;
        g_w1[jj] = sg[jj] + ww;
    }
}

// ---------------- P3a: x -> A-fragment layout (direct gmem, no smem) ----------------
__global__ void __launch_bounds__(256) k_convx(const float* __restrict__ x) {
    const int rt = blockIdx.x;
    const int w = threadIdx.x >> 5, lane = threadIdx.x & 31;
    const float* xr0 = x + ((size_t)rt * 16 + (lane >> 2)) * DDIM;
    const float* xr1 = xr0 + 8 * DDIM;
    #pragma unroll
    for (int i = 0; i < 8; i++) {
        int gg = i * 8 + w;
        int k0 = gg * 16 + 2 * (lane & 3);
        float2 a = *(const float2*)(xr0 + k0);
        float2 b = *(const float2*)(xr1 + k0);
        float2 c = *(const float2*)(xr0 + k0 + 8);
        float2 d = *(const float2*)(xr1 + k0 + 8);
        uint4 v;
        v.x = packhf(a.x, a.y);
        v.y = packhf(b.x, b.y);
        v.z = packhf(c.x, c.y);
        v.w = packhf(d.x, d.y);
        g_xB[(size_t)(rt * 64 + gg) * 32 + lane] = v;
    }
}

// ---------------- P3b: W -> B-fragment layout (direct gmem, no smem) ----------------
__global__ void __launch_bounds__(256) k_convw(const float* __restrict__ W) {
    const int ctp = blockIdx.x;
    const int w = threadIdx.x >> 5, lane = threadIdx.x & 31;
    const float* wr0 = W + ((size_t)ctp * 16 + (lane >> 2)) * DDIM;
    const float* wr1 = wr0 + 8 * DDIM;
    #pragma unroll
    for (int i = 0; i < 8; i++) {
        int gg = i * 8 + w;
        int k0 = gg * 16 + 2 * (lane & 3);
        float2 a = *(const float2*)(wr0 + k0);
        float2 b = *(const float2*)(wr0 + k0 + 8);
        float2 c = *(const float2*)(wr1 + k0);
        float2 d = *(const float2*)(wr1 + k0 + 8);
        uint4 v;
        v.x = packhf(a.x, a.y);
        v.y = packhf(b.x, b.y);
        v.z = packhf(c.x, c.y);
        v.w = packhf(d.x, d.y);
        g_wB[(size_t)(ctp * 64 + gg) * 32 + lane] = v;
    }
}

// ---------------- P3c: barrier-free GEMM + row sum-of-squares (unchanged from R12) ----------------
__global__ void __launch_bounds__(256, 2) k_norm(int B) {
    __shared__ float red2[128 * 2];
    const int tid  = threadIdx.x;
    const int lane = tid & 31;
    const int w    = tid >> 5;
    const int mrow = (w & 3) * 32;
    const int cg   = w >> 2;
    const int yg   = blockIdx.y;

    const uint4* xb = g_xB + ((size_t)(blockIdx.x * 8 + (w & 3) * 2) * 64) * 32 + lane;
    const uint4* wb = g_wB + ((size_t)(yg * 8 + cg * 4) * 64) * 32 + lane;

    float acc[2][8][4];
    #pragma unroll
    for (int mt = 0; mt < 2; mt++)
        #pragma unroll
        for (int nt = 0; nt < 8; nt++)
            #pragma unroll
            for (int q = 0; q < 4; q++) acc[mt][nt][q] = 0.0f;

    uint4 A[2], Bv[4];
    #pragma unroll
    for (int mt = 0; mt < 2; mt++) A[mt] = xb[mt * 2048];
    #pragma unroll
    for (int p = 0; p < 4; p++) Bv[p] = wb[p * 2048];

    #pragma unroll 4
    for (int gg = 0; gg < 64; gg++) {
        uint4 A2[2], B2[4];
        if (gg < 63) {
            const uint4* xn = xb + (gg + 1) * 32;
            const uint4* wn = wb + (gg + 1) * 32;
            #pragma unroll
            for (int mt = 0; mt < 2; mt++) A2[mt] = xn[mt * 2048];
            #pragma unroll
            for (int p = 0; p < 4; p++) B2[p] = wn[p * 2048];
        }
        #pragma unroll
        for (int mt = 0; mt < 2; mt++) {
            #pragma unroll
            for (int p = 0; p < 4; p++) {
                MMA_F16(acc[mt][2 * p],     A[mt].x, A[mt].y, A[mt].z, A[mt].w, Bv[p].x, Bv[p].y);
                MMA_F16(acc[mt][2 * p + 1], A[mt].x, A[mt].y, A[mt].z, A[mt].w, Bv[p].z, Bv[p].w);
            }
        }
        #pragma unroll
        for (int mt = 0; mt < 2; mt++) A[mt] = A2[mt];
        #pragma unroll
        for (int p = 0; p < 4; p++) Bv[p] = B2[p];
    }

    #pragma unroll
    for (int mt = 0; mt < 2; mt++) {
        #pragma unroll
        for (int h = 0; h < 2; h++) {
            float s = 0.0f;
            #pragma unroll
            for (int nt = 0; nt < 8; nt++) {
                float a = acc[mt][nt][2 * h], b = acc[mt][nt][2 * h + 1];
                s = fmaf(a, a, fmaf(b, b, s));
            }
            s += __shfl_xor_sync(0xffffffffu, s, 1);
            s += __shfl_xor_sync(0xffffffffu, s, 2);
            if ((lane & 3) == 0) {
                int rloc = mrow + mt * 16 + (lane >> 2) + h * 8;
                red2[rloc * 2 + cg] = s;
            }
        }
    }
    __syncthreads();
    if (tid < 128) {
        float s = red2[tid * 2] + red2[tid * 2 + 1];
        g_nsp[(size_t)yg * B + blockIdx.x * 128 + tid] = s;
    }
}

// ---------------- P4: agreement ----------------
__global__ void k_agree(int B) {
    int i = blockIdx.x * 256 + threadIdx.x;
    if (i < B) {
        float c = g_sc[1];
        float ns = g_nsp[i] + g_nsp[B + i] + g_nsp[2 * B + i] + g_nsp[3 * B + i];
        ns = fmaxf(ns, 1e-10f);
        float sc2 = c * ns / (1.0f + c * ns);
        g_agr[i] = sc2 * sqrtf(ns);
    }
}

// ---------------- MAIN: barrier-free GEMM + shfl softmax ----------------
// smem: b_s[64][520] f32 | bh[64][260] u32 | agrs[64]
#define BHS 260
#define SMEM_MAIN_BYTES ((64 * PAD + 64) * 4 + 64 * BHS * 4)

__global__ void __launch_bounds__(512, 1) k_main(float* __restrict__ out) {
    extern __shared__ float sm[];
    float*    b_s  = sm;                              // [64][PAD]
    unsigned* bh   = (unsigned*)(sm + 64 * PAD);      // [64][BHS]
    float*    agrs = (float*)(bh + 64 * BHS);         // [64]

    const int tid  = threadIdx.x;
    const int lane = tid & 31;
    const int wrp  = tid >> 5;
    const int row0 = blockIdx.x * 64;
    const float invT = g_sc[0];

    const int r  = tid >> 3;
    const int t8 = tid & 7;
    float* base = b_s + r * PAD + t8 * 4;
    unsigned* bhrow = bh + r * BHS + t8 * 2;

    if (tid < 64) agrs[tid] = g_agr[row0 + tid];
    float uj = g_u1[tid & 511];
    float wj = g_w1[tid & 511];
    __syncthreads();
    #pragma unroll 8
    for (int r2 = 0; r2 < 64; r2++)
        b_s[r2 * PAD + tid] = fmaf(agrs[r2], wj, uj);
    __syncthreads();

    const uint4* bbase = (const uint4*)g_AtB + (wrp * 2) * 32 + lane;

    for (int it = 0; it < 4; it++) {
        // ---- b += a * softmax(b/T); shfl reductions over 8-lane row groups ----
        float mx = -3.4e38f;
        #pragma unroll
        for (int j = 0; j < 16; j++) {
            float4 v = *(const float4*)(base + j * 32);
            mx = fmaxf(mx, fmaxf(fmaxf(v.x, v.y), fmaxf(v.z, v.w)));
        }
        #pragma unroll
        for (int o = 4; o > 0; o >>= 1) mx = fmaxf(mx, __shfl_xor_sync(0xffffffffu, mx, o));
        float m = mx;
        float s = 0.0f;
        #pragma unroll
        for (int j = 0; j < 16; j++) {
            float4 v = *(const float4*)(base + j * 32);
            s += __expf((v.x - m) * invT) + __expf((v.y - m) * invT)
               + __expf((v.z - m) * invT) + __expf((v.w - m) * invT);
        }
        #pragma unroll
        for (int o = 4; o > 0; o >>= 1) s += __shfl_xor_sync(0xffffffffu, s, o);
        float aS = agrs[r] / s;
        #pragma unroll
        for (int j = 0; j < 16; j++) {
            float4 v = *(const float4*)(base + j * 32);
            v.x = fmaf(aS, __expf((v.x - m) * invT), v.x);
            v.y = fmaf(aS, __expf((v.y - m) * invT), v.y);
            v.z = fmaf(aS, __expf((v.z - m) * invT), v.z);
            v.w = fmaf(aS, __expf((v.w - m) * invT), v.w);
            *(float4*)(base + j * 32) = v;
            *(uint2*)(bhrow + j * 16) = make_uint2(packhf(v.x, v.y), packhf(v.z, v.w));
        }
        __syncthreads();   // bh ready for all warps

        // ---- d = b @ AtH: zero-barrier GEMM (B from L2 via LDG, A from bh) ----
        float acc[4][4][4];
        #pragma unroll
        for (int mt = 0; mt < 4; mt++)
            #pragma unroll
            for (int nt = 0; nt < 4; nt++)
                #pragma unroll
                for (int q = 0; q < 4; q++) acc[mt][nt][q] = 0.0f;

        uint4 B0 = bbase[0], B1 = bbase[32];
        #pragma unroll 4
        for (int gg = 0; gg < 32; gg++) {
            uint4 C0, C1;
            if (gg < 31) {
                const uint4* nb = bbase + (gg + 1) * 1024;
                C0 = nb[0]; C1 = nb[32];
            }
            const int kb = gg * 8 + (lane & 3);
            #pragma unroll
            for (int mt = 0; mt < 4; mt++) {
                int ra = (mt * 16 + (lane >> 2)) * BHS + kb;
                unsigned a0 = bh[ra];
                unsigned a1 = bh[ra + 8 * BHS];
                unsigned a2 = bh[ra + 4];
                unsigned a3 = bh[ra + 8 * BHS + 4];
                MMA_F16(acc[mt][0], a0, a1, a2, a3, B0.x, B0.y);
                MMA_F16(acc[mt][1], a0, a1, a2, a3, B0.z, B0.w);
                MMA_F16(acc[mt][2], a0, a1, a2, a3, B1.x, B1.y);
                MMA_F16(acc[mt][3], a0, a1, a2, a3, B1.z, B1.w);
            }
            B0 = C0; B1 = C1;
        }

        // ---- b += d ----
        #pragma unroll
        for (int mt = 0; mt < 4; mt++) {
            int row = mt * 16 + (lane >> 2);
            #pragma unroll
            for (int nt = 0; nt < 4; nt++) {
                int col = wrp * 32 + nt * 8 + 2 * (lane & 3);
                float* p = b_s + row * PAD + col;
                p[0]           += acc[mt][nt][0];
                p[1]           += acc[mt][nt][1];
                p[8 * PAD]     += acc[mt][nt][2];
                p[8 * PAD + 1] += acc[mt][nt][3];
            }
        }
        __syncthreads();   // b_s updated before next softmax / final
    }

    // ---- theta = softmax(b/T) -> out ----
    {
        float mx = -3.4e38f;
        #pragma unroll
        for (int j = 0; j < 16; j++) {
            float4 v = *(const float4*)(base + j * 32);
            mx = fmaxf(mx, fmaxf(fmaxf(v.x, v.y), fmaxf(v.z, v.w)));
        }
        #pragma unroll
        for (int o = 4; o > 0; o >>= 1) mx = fmaxf(mx, __shfl_xor_sync(0xffffffffu, mx, o));
        float m = mx;
        float s = 0.0f;
        #pragma unroll
        for (int j = 0; j < 16; j++) {
            float4 v = *(const float4*)(base + j * 32);
            s += __expf((v.x - m) * invT) + __expf((v.y - m) * invT)
               + __expf((v.z - m) * invT) + __expf((v.w - m) * invT);
        }
        #pragma unroll
        for (int o = 4; o > 0; o >>= 1) s += __shfl_xor_sync(0xffffffffu, s, o);
        float iS = 1.0f / s;
        float* op = out + (size_t)(row0 + r) * KCAP + t8 * 4;
        #pragma unroll
        for (int j = 0; j < 16; j++) {
            float4 v = *(const float4*)(base + j * 32);
            float4 o;
            o.x = __expf((v.x - m) * invT) * iS;
            o.y = __expf((v.y - m) * invT) * iS;
            o.z = __expf((v.z - m) * invT) * iS;
            o.w = __expf((v.w - m) * invT) * iS;
            *(float4*)(op + j * 32) = o;
        }
    }
}

// ---------------- launcher ----------------
extern "C" void kernel_launch(void* const* d_in, const int* in_sizes, int n_in,
                              void* d_out, int out_size) {
    const float* x    = (const float*)d_in[0];
    const float* W    = (const float*)d_in[1];
    const float* A    = (const float*)d_in[2];
    const float* lT   = (const float*)d_in[3];
    const float* lc   = (const float*)d_in[4];
    const float* brun = (const float*)d_in[5];
    const void*  temp = d_in[6];
    const int B = in_sizes[0] / DDIM;   // 16384

    cudaFuncSetAttribute(k_main, cudaFuncAttributeMaxDynamicSharedMemorySize,
                         SMEM_MAIN_BYTES);

    k_scalars<<<1, 32>>>(lT, lc, temp);
    k_adiff<<<KCAP, 256>>>(A);
    k_prep<<<16, 256>>>(brun);
    k_convx<<<B / 16, 256>>>(x);
    k_convw<<<KCAP / 16, 256>>>(W);
    k_norm<<<dim3(B / 128, 4), 256>>>(B);
    k_agree<<<(B + 255) / 256, 256>>>(B);
    k_main<<<B / 64, 512, SMEM_MAIN_BYTES>>>((float*)d_out);
}